// round 13
// baseline (speedup 1.0000x reference)
#include <cuda_runtime.h>
#include <cuda_fp16.h>
#include <cstdint>

#define NB 16
#define NS 2048
#define ND 64
#define NO 128
#define KSPLIT 16
#define KC 128            // K per g1 block

// ---------------- scratch (no allocs allowed) ------------------------------
__device__ float  g_Y[NB * NO * ND];                // fp32 Y, RED-accumulated
__device__ __half g_xh[NB * NS * ND];               // x fp16, layout = x
__device__ __half g_wh[NO * NS];                    // W fp16, layout = W

// ---------------- helpers --------------------------------------------------
__device__ __forceinline__ uint32_t smem_u32(const void* p) {
    uint32_t a;
    asm("{ .reg .u64 t; cvta.to.shared.u64 t, %1; cvt.u32.u64 %0, t; }"
        : "=r"(a) : "l"(p));
    return a;
}
__device__ __forceinline__ void ldm_x4(uint32_t* r, uint32_t addr) {
    asm volatile("ldmatrix.sync.aligned.m8n8.x4.shared.b16 {%0,%1,%2,%3}, [%4];"
                 : "=r"(r[0]), "=r"(r[1]), "=r"(r[2]), "=r"(r[3]) : "r"(addr));
}
__device__ __forceinline__ void ldm_x4t(uint32_t* r, uint32_t addr) {
    asm volatile("ldmatrix.sync.aligned.m8n8.x4.trans.shared.b16 {%0,%1,%2,%3}, [%4];"
                 : "=r"(r[0]), "=r"(r[1]), "=r"(r[2]), "=r"(r[3]) : "r"(addr));
}
__device__ __forceinline__ void mma_f16(float* c, const uint32_t* a,
                                        const uint32_t* b) {
    asm volatile(
        "mma.sync.aligned.m16n8k16.row.col.f32.f16.f16.f32 "
        "{%0,%1,%2,%3}, {%4,%5,%6,%7}, {%8,%9}, {%0,%1,%2,%3};"
        : "+f"(c[0]), "+f"(c[1]), "+f"(c[2]), "+f"(c[3])
        : "r"(a[0]), "r"(a[1]), "r"(a[2]), "r"(a[3]), "r"(b[0]), "r"(b[1]));
}
__device__ __forceinline__ void cp_async16(uint32_t saddr, const void* g) {
    asm volatile("cp.async.cg.shared.global [%0], [%1], 16;"
                 :: "r"(saddr), "l"(g) : "memory");
}
#define CP_COMMIT() asm volatile("cp.async.commit_group;" ::: "memory")
#define CP_WAIT(n)  asm volatile("cp.async.wait_group %0;" :: "n"(n) : "memory")

__device__ __forceinline__ void red_f32(float* p, float v) {
    asm volatile("red.global.add.f32 [%0], %1;" :: "l"(p), "f"(v) : "memory");
}
__device__ __forceinline__ uint32_t hpack2(float a, float b) {
    __half2 h = __floats2half2_rn(a, b);
    return *(uint32_t*)&h;
}

// ===========================================================================
// prep: fp32 -> fp16 of x and W (layout-preserving) + zero g_Y.
// blocks 0..511 -> x (524288 float4), 512..575 -> W (65536 float4).
// blocks 0..127 additionally zero g_Y (32768 float4).
// ===========================================================================
__global__ __launch_bounds__(256) void prep(const float* __restrict__ x,
                                            const float* __restrict__ W) {
    const int bid = blockIdx.x;
    const float4* src;
    uint2* dst;
    size_t base;
    if (bid < 512) {
        src = (const float4*)x;  dst = (uint2*)g_xh;  base = (size_t)bid * 1024;
    } else {
        src = (const float4*)W;  dst = (uint2*)g_wh;  base = (size_t)(bid - 512) * 1024;
    }
#pragma unroll
    for (int j = 0; j < 4; j++) {
        size_t e = base + threadIdx.x + j * 256;
        float4 v = src[e];
        dst[e] = make_uint2(hpack2(v.x, v.y), hpack2(v.z, v.w));
    }
    if (bid < 128)
        ((float4*)g_Y)[bid * 256 + threadIdx.x] = make_float4(0.f, 0.f, 0.f, 0.f);
}

// ===========================================================================
// G1: g_Y[b][o][d] += W[o, kslice] @ x[b, kslice, d]  (RED-accumulated)
// 1-term fp16, 2-phase cp.async pipeline (k halves). grid (KSPLIT=16, NB)
// = 256 CTAs, 256 thr (8 warps 4x2), K=128 per CTA. smem 52KB, 3 CTAs/SM.
// ===========================================================================
#define G1_WAHI 0
#define G1_XBHI 34816
#define G1_SMEM 53248

__global__ __launch_bounds__(256, 3) void g1() {
    extern __shared__ char sm[];
    const int tid = threadIdx.x, wid = tid >> 5, lane = tid & 31;
    const int ks = blockIdx.x, b = blockIdx.y;
    const int wm = wid & 3, wn = wid >> 2;
    const int o0 = wm * 32, d0 = wn * 32;
    const int kbase = ks * KC;

    const uint32_t s_wahi = smem_u32(sm + G1_WAHI);
    const uint32_t s_xbhi = smem_u32(sm + G1_XBHI);

    // Phase-1 loads: k 0-63  (W chunks c0-7, x rows 0-63)
#pragma unroll
    for (int j = 0; j < 4; j++) {
        int idx = tid + j * 256;                  // 1024 chunks
        int o = idx >> 3, c = idx & 7;
        cp_async16(s_wahi + o * 272 + c * 16, &g_wh[(size_t)o * NS + kbase + c * 8]);
    }
#pragma unroll
    for (int j = 0; j < 2; j++) {
        int idx = tid + j * 256;                  // 512 chunks
        int k = idx >> 3, c = idx & 7;
        cp_async16(s_xbhi + k * 144 + c * 16,
                   &g_xh[((size_t)b * NS + kbase + k) * ND + c * 8]);
    }
    CP_COMMIT();
    // Phase-2 loads: k 64-127 (W chunks c8-15, x rows 64-127)
#pragma unroll
    for (int j = 0; j < 4; j++) {
        int idx = tid + j * 256;
        int o = idx >> 3, c = (idx & 7) + 8;
        cp_async16(s_wahi + o * 272 + c * 16, &g_wh[(size_t)o * NS + kbase + c * 8]);
    }
#pragma unroll
    for (int j = 0; j < 2; j++) {
        int idx = tid + j * 256;
        int k = (idx >> 3) + 64, c = idx & 7;
        cp_async16(s_xbhi + k * 144 + c * 16,
                   &g_xh[((size_t)b * NS + kbase + k) * ND + c * 8]);
    }
    CP_COMMIT();

    float acc[2][4][4];
#pragma unroll
    for (int mt = 0; mt < 2; mt++)
#pragma unroll
        for (int nt = 0; nt < 4; nt++)
#pragma unroll
            for (int q = 0; q < 4; q++) acc[mt][nt][q] = 0.f;

    CP_WAIT(1);
    __syncthreads();

#pragma unroll
    for (int half = 0; half < 2; half++) {
#pragma unroll
        for (int k2 = 0; k2 < 4; k2++) {
            const int kk = half * 4 + k2;
            uint32_t ahi[2][4];
#pragma unroll
            for (int mt = 0; mt < 2; mt++) {
                uint32_t off = (uint32_t)((o0 + mt * 16 + (lane & 15)) * 272 +
                                          kk * 32 + (lane >> 4) * 16);
                ldm_x4(ahi[mt], s_wahi + off);
            }
            uint32_t bhi[2][4];
#pragma unroll
            for (int p = 0; p < 2; p++) {
                uint32_t off = (uint32_t)((kk * 16 + (lane & 15)) * 144 +
                                          (d0 + p * 16 + (lane >> 4) * 8) * 2);
                ldm_x4t(bhi[p], s_xbhi + off);
            }
#pragma unroll
            for (int mt = 0; mt < 2; mt++)
#pragma unroll
                for (int nt = 0; nt < 4; nt++)
                    mma_f16(acc[mt][nt], ahi[mt], &bhi[nt >> 1][(nt & 1) * 2]);
        }
        if (half == 0) {
            CP_WAIT(0);
            __syncthreads();
        }
    }

    // epilogue -> RED-accumulate into g_Y fp32
    float* Yp = g_Y + (size_t)b * NO * ND;
#pragma unroll
    for (int mt = 0; mt < 2; mt++)
#pragma unroll
        for (int nt = 0; nt < 4; nt++) {
            int o = o0 + mt * 16 + (lane >> 2);
            int d = d0 + nt * 8 + (lane & 3) * 2;
            float* p = Yp + (size_t)o * ND + d;
            red_f32(p, acc[mt][nt][0]);
            red_f32(p + 1, acc[mt][nt][1]);
            red_f32(p + 8 * ND, acc[mt][nt][2]);
            red_f32(p + 8 * ND + 1, acc[mt][nt][3]);
        }
}

// ===========================================================================
// G2: out[b][s][o] = x[b,s,:] . Y[b,o,:] + bias[o]
// 1-term fp16. Tile M=128 s, N=128 o, K=64. grid (NS/128, NB) = 256 CTAs,
// 256 thr (8 warps 4x2, each warp 2 m-tiles x 8 n-tiles). 2 CTAs/SM.
// X via cp.async fp16; Y loaded fp32 (L2-hot) + converted inline.
// smem: XS [128][144], YS [128][144], bias. 37KB.
// ===========================================================================
#define G2_XHI 0
#define G2_YHI 18432
#define G2_BIAS 36864
#define G2_SMEM 37376

__global__ __launch_bounds__(256, 2) void g2(const float* __restrict__ bias,
                                             float* __restrict__ out) {
    extern __shared__ char sm[];
    float* bias_s = (float*)(sm + G2_BIAS);
    const int tid = threadIdx.x, wid = tid >> 5, lane = tid & 31;
    const int st = blockIdx.x, b = blockIdx.y;
    const int s0 = st * 128;
    const int wm = wid & 3, wn = wid >> 2;
    const int s0w = wm * 16, o0w = wn * 64;

    const uint32_t s_xhi = smem_u32(sm + G2_XHI);
    const uint32_t s_yhi = smem_u32(sm + G2_YHI);

    // X tile: 128 s x 8 chunks via cp.async (issued first, overlaps Y path)
#pragma unroll
    for (int j = 0; j < 4; j++) {
        int idx = tid + j * 256;
        int s = idx >> 3, c = idx & 7;
        cp_async16(s_xhi + s * 144 + c * 16,
                   &g_xh[((size_t)b * NS + s0 + s) * ND + c * 8]);
    }
    CP_COMMIT();

    // Y tile fp32 [128 o][64 d] -> fp16 smem (2048 float4, 8 per thread)
    const float4* yg = (const float4*)(g_Y + (size_t)b * NO * ND);
#pragma unroll
    for (int j = 0; j < 8; j++) {
        int idx = tid + j * 256;
        int o = idx >> 4, d4 = (idx & 15) * 4;
        float4 v = yg[idx];
        *(uint2*)(sm + G2_YHI + o * 144 + d4 * 2) =
            make_uint2(hpack2(v.x, v.y), hpack2(v.z, v.w));
    }
    if (tid < NO) bias_s[tid] = bias[tid];
    CP_WAIT(0);
    __syncthreads();

    float acc[2][8][4];
#pragma unroll
    for (int mt = 0; mt < 2; mt++)
#pragma unroll
        for (int nt = 0; nt < 8; nt++)
#pragma unroll
            for (int q = 0; q < 4; q++) acc[mt][nt][q] = 0.f;

#pragma unroll
    for (int kk = 0; kk < 4; kk++) {
        uint32_t ahi[2][4];
#pragma unroll
        for (int mt = 0; mt < 2; mt++) {
            uint32_t off = (uint32_t)((s0w + mt * 64 + (lane & 15)) * 144 +
                                      kk * 32 + (lane >> 4) * 16);
            ldm_x4(ahi[mt], s_xhi + off);
        }
        uint32_t bhi[4][4];
#pragma unroll
        for (int p = 0; p < 4; p++) {
            uint32_t off = (uint32_t)((o0w + p * 16 + (lane >> 4) * 8 + (lane & 7)) * 144 +
                                      kk * 32 + ((lane >> 3) & 1) * 16);
            ldm_x4(bhi[p], s_yhi + off);
        }
#pragma unroll
        for (int mt = 0; mt < 2; mt++)
#pragma unroll
            for (int nt = 0; nt < 8; nt++)
                mma_f16(acc[mt][nt], ahi[mt], &bhi[nt >> 1][(nt & 1) * 2]);
    }

    // epilogue: +bias -> out
#pragma unroll
    for (int mt = 0; mt < 2; mt++) {
        const int srow = s0 + s0w + mt * 64 + (lane >> 2);
#pragma unroll
        for (int nt = 0; nt < 8; nt++) {
            int o = o0w + nt * 8 + (lane & 3) * 2;
            float2 bb = *(float2*)&bias_s[o];
            float* p0 = out + ((size_t)b * NS + srow) * NO + o;
            *(float2*)p0 = make_float2(acc[mt][nt][0] + bb.x, acc[mt][nt][1] + bb.y);
            *(float2*)(p0 + 8 * NO) =
                make_float2(acc[mt][nt][2] + bb.x, acc[mt][nt][3] + bb.y);
        }
    }
}

// ===========================================================================
extern "C" void kernel_launch(void* const* d_in, const int* in_sizes, int n_in,
                              void* d_out, int out_size) {
    const float* x = nullptr;
    const float* W = nullptr;
    const float* bias = nullptr;
    for (int i = 0; i < n_in; i++) {
        if (in_sizes[i] == NB * NS * ND)      x = (const float*)d_in[i];
        else if (in_sizes[i] == NO * NS)      W = (const float*)d_in[i];
        else if (in_sizes[i] == NO)           bias = (const float*)d_in[i];
    }
    float* out = (float*)d_out;

    cudaFuncSetAttribute(g1, cudaFuncAttributeMaxDynamicSharedMemorySize, G1_SMEM);
    cudaFuncSetAttribute(g2, cudaFuncAttributeMaxDynamicSharedMemorySize, G2_SMEM);

    prep<<<576, 256>>>(x, W);
    g1<<<dim3(KSPLIT, NB), 256, G1_SMEM>>>();
    g2<<<dim3(NS / 128, NB), 256, G2_SMEM>>>(bias, out);
}

// round 14
// speedup vs baseline: 1.0120x; 1.0120x over previous
#include <cuda_runtime.h>
#include <cuda_fp16.h>
#include <cstdint>

#define NB 16
#define NS 2048
#define ND 64
#define NO 128
#define KSPLIT 16
#define KC 128            // K per g1 block

// ---------------- scratch (no allocs allowed) ------------------------------
__device__ float  g_Y[NB * NO * ND];                // fp32 Y, RED-accumulated
__device__ __half g_wh[NO * NS];                    // W fp16, layout = W

// ---------------- helpers --------------------------------------------------
__device__ __forceinline__ uint32_t smem_u32(const void* p) {
    uint32_t a;
    asm("{ .reg .u64 t; cvta.to.shared.u64 t, %1; cvt.u32.u64 %0, t; }"
        : "=r"(a) : "l"(p));
    return a;
}
__device__ __forceinline__ void ldm_x4(uint32_t* r, uint32_t addr) {
    asm volatile("ldmatrix.sync.aligned.m8n8.x4.shared.b16 {%0,%1,%2,%3}, [%4];"
                 : "=r"(r[0]), "=r"(r[1]), "=r"(r[2]), "=r"(r[3]) : "r"(addr));
}
__device__ __forceinline__ void ldm_x4t(uint32_t* r, uint32_t addr) {
    asm volatile("ldmatrix.sync.aligned.m8n8.x4.trans.shared.b16 {%0,%1,%2,%3}, [%4];"
                 : "=r"(r[0]), "=r"(r[1]), "=r"(r[2]), "=r"(r[3]) : "r"(addr));
}
__device__ __forceinline__ void mma_f16(float* c, const uint32_t* a,
                                        const uint32_t* b) {
    asm volatile(
        "mma.sync.aligned.m16n8k16.row.col.f32.f16.f16.f32 "
        "{%0,%1,%2,%3}, {%4,%5,%6,%7}, {%8,%9}, {%0,%1,%2,%3};"
        : "+f"(c[0]), "+f"(c[1]), "+f"(c[2]), "+f"(c[3])
        : "r"(a[0]), "r"(a[1]), "r"(a[2]), "r"(a[3]), "r"(b[0]), "r"(b[1]));
}
__device__ __forceinline__ void cp_async16(uint32_t saddr, const void* g) {
    asm volatile("cp.async.cg.shared.global [%0], [%1], 16;"
                 :: "r"(saddr), "l"(g) : "memory");
}
#define CP_COMMIT() asm volatile("cp.async.commit_group;" ::: "memory")
#define CP_WAIT(n)  asm volatile("cp.async.wait_group %0;" :: "n"(n) : "memory")

__device__ __forceinline__ void red_f32(float* p, float v) {
    asm volatile("red.global.add.f32 [%0], %1;" :: "l"(p), "f"(v) : "memory");
}
__device__ __forceinline__ uint32_t hpack2(float a, float b) {
    __half2 h = __floats2half2_rn(a, b);
    return *(uint32_t*)&h;
}

// ===========================================================================
// prep_w: fp32 -> fp16 of W (layout-preserving) + zero g_Y.
// 128 blocks x 256 thr: W 65536 float4 (2/thread), Y 32768 float4 (1/thread).
// ===========================================================================
__global__ __launch_bounds__(256) void prep_w(const float* __restrict__ W) {
    const int bid = blockIdx.x, tid = threadIdx.x;
    const float4* src = (const float4*)W;
    uint2* dst = (uint2*)g_wh;
#pragma unroll
    for (int j = 0; j < 2; j++) {
        size_t e = (size_t)bid * 512 + tid + j * 256;
        float4 v = src[e];
        dst[e] = make_uint2(hpack2(v.x, v.y), hpack2(v.z, v.w));
    }
    ((float4*)g_Y)[bid * 256 + tid] = make_float4(0.f, 0.f, 0.f, 0.f);
}

// ===========================================================================
// G1: g_Y[b][o][d] += W[o, kslice] @ x[b, kslice, d]  (RED-accumulated)
// 1-term fp16. W via 2-phase cp.async fp16 pipeline; x loaded fp32 inline
// (batched LDG.128 overlapping the W stream) + converted to smem.
// grid (KSPLIT=16, NB) = 256 CTAs, 256 thr (8 warps 4x2). smem 52KB, 3/SM.
// ===========================================================================
#define G1_WAHI 0
#define G1_XBHI 34816
#define G1_SMEM 53248

__global__ __launch_bounds__(256, 3) void g1(const float* __restrict__ x) {
    extern __shared__ char sm[];
    const int tid = threadIdx.x, wid = tid >> 5, lane = tid & 31;
    const int ks = blockIdx.x, b = blockIdx.y;
    const int wm = wid & 3, wn = wid >> 2;
    const int o0 = wm * 32, d0 = wn * 32;
    const int kbase = ks * KC;

    const uint32_t s_wahi = smem_u32(sm + G1_WAHI);
    const uint32_t s_xbhi = smem_u32(sm + G1_XBHI);

    // W phase-1 (k 0-63) + phase-2 (k 64-127) cp.async streams
#pragma unroll
    for (int j = 0; j < 4; j++) {
        int idx = tid + j * 256;
        int o = idx >> 3, c = idx & 7;
        cp_async16(s_wahi + o * 272 + c * 16, &g_wh[(size_t)o * NS + kbase + c * 8]);
    }
    CP_COMMIT();
#pragma unroll
    for (int j = 0; j < 4; j++) {
        int idx = tid + j * 256;
        int o = idx >> 3, c = (idx & 7) + 8;
        cp_async16(s_wahi + o * 272 + c * 16, &g_wh[(size_t)o * NS + kbase + c * 8]);
    }
    CP_COMMIT();

    // x tile [128 k][64 d] fp32 inline: 2048 float4, 8/thread in 2 batches.
    // LDG round trip overlaps with the W cp.async stream above.
#pragma unroll
    for (int batch = 0; batch < 2; batch++) {
        float4 v[4];
#pragma unroll
        for (int j = 0; j < 4; j++) {
            int idx = tid + (batch * 4 + j) * 256;
            int k = idx >> 4, d4 = (idx & 15) * 4;
            v[j] = *(const float4*)(x + ((size_t)b * NS + kbase + k) * ND + d4);
        }
#pragma unroll
        for (int j = 0; j < 4; j++) {
            int idx = tid + (batch * 4 + j) * 256;
            int k = idx >> 4, d4 = (idx & 15) * 4;
            *(uint2*)(sm + G1_XBHI + k * 144 + d4 * 2) =
                make_uint2(hpack2(v[j].x, v[j].y), hpack2(v[j].z, v[j].w));
        }
    }

    float acc[2][4][4];
#pragma unroll
    for (int mt = 0; mt < 2; mt++)
#pragma unroll
        for (int nt = 0; nt < 4; nt++)
#pragma unroll
            for (int q = 0; q < 4; q++) acc[mt][nt][q] = 0.f;

    CP_WAIT(1);
    __syncthreads();

#pragma unroll
    for (int half = 0; half < 2; half++) {
#pragma unroll
        for (int k2 = 0; k2 < 4; k2++) {
            const int kk = half * 4 + k2;
            uint32_t ahi[2][4];
#pragma unroll
            for (int mt = 0; mt < 2; mt++) {
                uint32_t off = (uint32_t)((o0 + mt * 16 + (lane & 15)) * 272 +
                                          kk * 32 + (lane >> 4) * 16);
                ldm_x4(ahi[mt], s_wahi + off);
            }
            uint32_t bhi[2][4];
#pragma unroll
            for (int p = 0; p < 2; p++) {
                uint32_t off = (uint32_t)((kk * 16 + (lane & 15)) * 144 +
                                          (d0 + p * 16 + (lane >> 4) * 8) * 2);
                ldm_x4t(bhi[p], s_xbhi + off);
            }
#pragma unroll
            for (int mt = 0; mt < 2; mt++)
#pragma unroll
                for (int nt = 0; nt < 4; nt++)
                    mma_f16(acc[mt][nt], ahi[mt], &bhi[nt >> 1][(nt & 1) * 2]);
        }
        if (half == 0) {
            CP_WAIT(0);
            __syncthreads();
        }
    }

    // epilogue -> RED-accumulate into g_Y fp32
    float* Yp = g_Y + (size_t)b * NO * ND;
#pragma unroll
    for (int mt = 0; mt < 2; mt++)
#pragma unroll
        for (int nt = 0; nt < 4; nt++) {
            int o = o0 + mt * 16 + (lane >> 2);
            int d = d0 + nt * 8 + (lane & 3) * 2;
            float* p = Yp + (size_t)o * ND + d;
            red_f32(p, acc[mt][nt][0]);
            red_f32(p + 1, acc[mt][nt][1]);
            red_f32(p + 8 * ND, acc[mt][nt][2]);
            red_f32(p + 8 * ND + 1, acc[mt][nt][3]);
        }
}

// ===========================================================================
// G2: out[b][s][o] = x[b,s,:] . Y[b,o,:] + bias[o]
// 1-term fp16. Tile M=128 s, N=128 o, K=64. grid (NS/128, NB) = 256 CTAs,
// 256 thr (8 warps 4x2, each warp 2 m x 8 n tiles). 2 CTAs/SM.
// x fp32 inline (batched LDG, DRAM) + Y fp32 inline (L2-hot), both -> fp16.
// smem: XS [128][144], YS [128][144], bias. 37KB.
// ===========================================================================
#define G2_XHI 0
#define G2_YHI 18432
#define G2_BIAS 36864
#define G2_SMEM 37376

__global__ __launch_bounds__(256, 2) void g2(const float* __restrict__ x,
                                             const float* __restrict__ bias,
                                             float* __restrict__ out) {
    extern __shared__ char sm[];
    float* bias_s = (float*)(sm + G2_BIAS);
    const int tid = threadIdx.x, wid = tid >> 5, lane = tid & 31;
    const int st = blockIdx.x, b = blockIdx.y;
    const int s0 = st * 128;
    const int wm = wid & 3, wn = wid >> 2;
    const int s0w = wm * 16, o0w = wn * 64;

    const uint32_t s_xhi = smem_u32(sm + G2_XHI);
    const uint32_t s_yhi = smem_u32(sm + G2_YHI);

    // x tile [128 s][64 d] fp32 (DRAM) — 8 f4/thread, front-batched for MLP
    float4 xv[8];
#pragma unroll
    for (int j = 0; j < 8; j++) {
        int idx = tid + j * 256;
        int s = idx >> 4, d4 = (idx & 15) * 4;
        xv[j] = *(const float4*)(x + ((size_t)b * NS + s0 + s) * ND + d4);
    }
    // Y tile [128 o][64 d] fp32 (L2-hot from g1 REDs)
    const float4* yg = (const float4*)(g_Y + (size_t)b * NO * ND);
#pragma unroll
    for (int j = 0; j < 8; j++) {
        int idx = tid + j * 256;
        int o = idx >> 4, d4 = (idx & 15) * 4;
        float4 v = yg[idx];
        *(uint2*)(sm + G2_YHI + o * 144 + d4 * 2) =
            make_uint2(hpack2(v.x, v.y), hpack2(v.z, v.w));
    }
#pragma unroll
    for (int j = 0; j < 8; j++) {
        int idx = tid + j * 256;
        int s = idx >> 4, d4 = (idx & 15) * 4;
        *(uint2*)(sm + G2_XHI + s * 144 + d4 * 2) =
            make_uint2(hpack2(xv[j].x, xv[j].y), hpack2(xv[j].z, xv[j].w));
    }
    if (tid < NO) bias_s[tid] = bias[tid];
    __syncthreads();

    float acc[2][8][4];
#pragma unroll
    for (int mt = 0; mt < 2; mt++)
#pragma unroll
        for (int nt = 0; nt < 8; nt++)
#pragma unroll
            for (int q = 0; q < 4; q++) acc[mt][nt][q] = 0.f;

#pragma unroll
    for (int kk = 0; kk < 4; kk++) {
        uint32_t ahi[2][4];
#pragma unroll
        for (int mt = 0; mt < 2; mt++) {
            uint32_t off = (uint32_t)((s0w + mt * 64 + (lane & 15)) * 144 +
                                      kk * 32 + (lane >> 4) * 16);
            ldm_x4(ahi[mt], s_xhi + off);
        }
        uint32_t bhi[4][4];
#pragma unroll
        for (int p = 0; p < 4; p++) {
            uint32_t off = (uint32_t)((o0w + p * 16 + (lane >> 4) * 8 + (lane & 7)) * 144 +
                                      kk * 32 + ((lane >> 3) & 1) * 16);
            ldm_x4(bhi[p], s_yhi + off);
        }
#pragma unroll
        for (int mt = 0; mt < 2; mt++)
#pragma unroll
            for (int nt = 0; nt < 8; nt++)
                mma_f16(acc[mt][nt], ahi[mt], &bhi[nt >> 1][(nt & 1) * 2]);
    }

    // epilogue: +bias -> out
#pragma unroll
    for (int mt = 0; mt < 2; mt++) {
        const int srow = s0 + s0w + mt * 64 + (lane >> 2);
#pragma unroll
        for (int nt = 0; nt < 8; nt++) {
            int o = o0w + nt * 8 + (lane & 3) * 2;
            float2 bb = *(float2*)&bias_s[o];
            float* p0 = out + ((size_t)b * NS + srow) * NO + o;
            *(float2*)p0 = make_float2(acc[mt][nt][0] + bb.x, acc[mt][nt][1] + bb.y);
            *(float2*)(p0 + 8 * NO) =
                make_float2(acc[mt][nt][2] + bb.x, acc[mt][nt][3] + bb.y);
        }
    }
}

// ===========================================================================
extern "C" void kernel_launch(void* const* d_in, const int* in_sizes, int n_in,
                              void* d_out, int out_size) {
    const float* x = nullptr;
    const float* W = nullptr;
    const float* bias = nullptr;
    for (int i = 0; i < n_in; i++) {
        if (in_sizes[i] == NB * NS * ND)      x = (const float*)d_in[i];
        else if (in_sizes[i] == NO * NS)      W = (const float*)d_in[i];
        else if (in_sizes[i] == NO)           bias = (const float*)d_in[i];
    }
    float* out = (float*)d_out;

    cudaFuncSetAttribute(g1, cudaFuncAttributeMaxDynamicSharedMemorySize, G1_SMEM);
    cudaFuncSetAttribute(g2, cudaFuncAttributeMaxDynamicSharedMemorySize, G2_SMEM);

    prep_w<<<128, 256>>>(W);
    g1<<<dim3(KSPLIT, NB), 256, G1_SMEM>>>(x);
    g2<<<dim3(NS / 128, NB), 256, G2_SMEM>>>(x, bias, out);
}